// round 5
// baseline (speedup 1.0000x reference)
#include <cuda_runtime.h>
#include <math.h>
#include <float.h>

#define TPB    512
#define KNN_K  16
#define NBX    32
#define NBY    32
#define NB2    (NBX * NBY)
#define FULLM  0xFFFFFFFFu
#define XMIN   (-4.8f)
#define XMAX   ( 4.8f)
#define BW     ((XMAX - XMIN) / (float)NBX)
#define INVBW  ((float)NBX / (XMAX - XMIN))
#define SAFE   1e-5f

// scratch (static device arrays; allocation-free rule)
__device__ int                g_idx [65536 * KNN_K];
__device__ float              g_w   [65536 * KNN_K];
__device__ float              g_Dfwd[65536];
__device__ unsigned long long g_Drev[65536];

// bucket-build scratch
__device__ int            g_hist[16 * NB2];          // zero-init; re-zeroed by k_scan
__device__ int            g_off [16 * (NB2 + 1)];
__device__ int            g_cur [16 * NB2];
__device__ float4         g_rc  [65536];             // reordered (x,y,z,|p|^2)
__device__ unsigned short g_rid [65536];             // orig index per position

__device__ __forceinline__ int bclamp(float v) {
    int ib = (int)((v - XMIN) * INVBW);
    return min(max(ib, 0), NBX - 1);
}
__device__ __forceinline__ int bucket_of(float x, float y) {
    return (bclamp(x) << 5) + bclamp(y);
}

// ---------- prepass ----------
__global__ void k_hist(const float* __restrict__ xyz, int N, int B)
{
    int t = blockIdx.x * blockDim.x + threadIdx.x;
    if (t >= B * N) return;
    int b = t / N, n = t - b * N;
    const float* X = xyz + (size_t)b * 3 * N;
    atomicAdd(&g_hist[b * NB2 + bucket_of(X[n], X[N + n])], 1);
}

__global__ void k_scan(int B)
{
    __shared__ int sm[NB2];
    int b = blockIdx.x, t = threadIdx.x;
    int v = g_hist[b * NB2 + t];
    g_hist[b * NB2 + t] = 0;                 // ready for next graph replay
    sm[t] = v;
    __syncthreads();
    // Hillis-Steele inclusive scan
    for (int d = 1; d < NB2; d <<= 1) {
        int add = (t >= d) ? sm[t - d] : 0;
        __syncthreads();
        sm[t] += add;
        __syncthreads();
    }
    int incl = sm[t];
    if (t == 0) g_off[b * (NB2 + 1)] = 0;
    g_off[b * (NB2 + 1) + t + 1] = incl;
    g_cur[b * NB2 + t] = incl - v;
}

__global__ void k_reorder(const float* __restrict__ xyz, int N, int B)
{
    int t = blockIdx.x * blockDim.x + threadIdx.x;
    if (t >= B * N) return;
    int b = t / N, n = t - b * N;
    const float* X = xyz + (size_t)b * 3 * N;
    float x = X[n], y = X[N + n], z = X[2 * N + n];
    float sq = fmaf(x, x, fmaf(y, y, z * z));
    int pos = atomicAdd(&g_cur[b * NB2 + bucket_of(x, y)], 1);
    g_rc [b * N + pos] = make_float4(x, y, z, sq);
    g_rid[b * N + pos] = (unsigned short)n;
}

// ---------- fused KNN + dense init ----------
__global__ void __launch_bounds__(TPB)
k_knn_init(float* __restrict__ out, int N, int B, int nb_knn)
{
    __shared__ int off[NB2 + 1];
    const int tid = threadIdx.x;

    if ((int)blockIdx.x >= nb_knn) {
        // ---------------- memset + diagonal path ----------------
        int bid = blockIdx.x - nb_knn;
        int b = bid / N;
        int i = bid - b * N;
        float4* row = reinterpret_cast<float4*>(out + ((size_t)b * N + i) * (size_t)N);
        int n4 = N >> 2;
        for (int f = tid; f < n4; f += TPB) {
            int j0 = f << 2;
            float4 v;
            v.x = (j0     == i) ? 1.0f : 0.0f;
            v.y = (j0 + 1 == i) ? 1.0f : 0.0f;
            v.z = (j0 + 2 == i) ? 1.0f : 0.0f;
            v.w = (j0 + 3 == i) ? 1.0f : 0.0f;
            row[f] = v;
        }
        return;
    }

    // ---------------- KNN path (candidates read from L2 via LDG) ----------------
    const int qpb = (TPB / 32) * 2;             // 32 queries per block
    const int blocks_per_b = N / qpb;
    const int b = blockIdx.x / blocks_per_b;
    const int qbase = (blockIdx.x - b * blocks_per_b) * qpb;
    const int bN = b * N;
    const float4* __restrict__ rcg = g_rc + bN;

    for (int i = tid; i <= NB2; i += TPB) off[i] = g_off[b * (NB2 + 1) + i];
    __syncthreads();

    const int warp = tid >> 5, lane = tid & 31;
    const int g = lane >> 4, sub = lane & 15;
    const int pos0 = qbase + warp * 2;          // bucket-sorted positions
    const float4 q0 = rcg[pos0];
    const float4 q1 = rcg[pos0 + 1];

    const float a0x = -2.0f * q0.x, a0y = -2.0f * q0.y, a0z = -2.0f * q0.z;
    const float a1x = -2.0f * q1.x, a1y = -2.0f * q1.y, a1z = -2.0f * q1.z;

    // seeded screening thresholds in e-space (expected ~40 pts in seed ball)
    const float seed0 = 0.1107f * __expf(q0.w * (1.0f / 3.0f)) - q0.w;
    const float seed1 = 0.1107f * __expf(q1.w * (1.0f / 3.0f)) - q1.w;

    float ld = FLT_MAX; int li = 0;
    float wt0, wt1;

    auto process = [&](int start, int end) {
        for (int p = start; p < end; p += 32) {
            int pp = p + lane;
            bool valid = pp < end;
            float4 c = rcg[valid ? pp : end - 1];
            float e0 = fmaf(a0x, c.x, fmaf(a0y, c.y, fmaf(a0z, c.z, c.w)));
            float e1 = fmaf(a1x, c.x, fmaf(a1y, c.y, fmaf(a1z, c.z, c.w)));
            unsigned bal0 = __ballot_sync(FULLM, valid && (e0 < wt0));
            unsigned bal1 = __ballot_sync(FULLM, valid && (e1 < wt1));
            if ((bal0 | bal1) == 0u) continue;
            do {
                int s0 = __ffs(bal0) - 1;
                int s1 = __ffs(bal1) - 1;
                float dd0 = __shfl_sync(FULLM, e0, s0 & 31);
                float dd1 = __shfl_sync(FULLM, e1, s1 & 31);
                bool have = g ? (bal1 != 0u) : (bal0 != 0u);
                float dd = g ? dd1 : dd0;
                int   jj = p + ((g ? s1 : s0) & 31);
                bool pr = have && (dd < ld);
                unsigned pb = __ballot_sync(FULLM, pr);
                float sld = __shfl_up_sync(FULLM, ld, 1);
                int   sli = __shfl_up_sync(FULLM, li, 1);
                bool prevpr = (sub > 0) && ((pb >> (lane - 1)) & 1u);
                if (pr) { ld = prevpr ? sld : dd; li = prevpr ? sli : jj; }
                bal0 &= bal0 - 1;
                bal1 &= bal1 - 1;
            } while (bal0 | bal1);
            wt0 = fminf(wt0, __shfl_sync(FULLM, ld, 15));
            wt1 = fminf(wt1, __shfl_sync(FULLM, ld, 31));
        }
    };

    // home buckets of the two queries (binary search over off[], warp-uniform)
    auto bsearch = [&](int p) {
        int lo = 0, hi = NB2 - 1;
        while (lo < hi) { int mid = (lo + hi + 1) >> 1; if (off[mid] <= p) lo = mid; else hi = mid - 1; }
        return lo;
    };
    const int h0 = bsearch(pos0);
    const int h1 = bsearch(pos0 + 1);          // h1 >= h0
    int ibx0 = h0 >> 5, ibx1 = h1 >> 5, iby0, iby1;
    if (ibx0 == ibx1) { iby0 = h0 & 31; iby1 = h1 & 31; }
    else              { iby0 = 0;       iby1 = NBY - 1; }

    for (int attempt = 0; attempt < 2; attempt++) {
        ld = FLT_MAX; li = 0;
        wt0 = attempt ? FLT_MAX : seed0;
        wt1 = attempt ? FLT_MAX : seed1;
        int bx0 = ibx0, bx1 = ibx1, by0 = iby0, by1 = iby1;

        for (int bx = bx0; bx <= bx1; ++bx)
            process(off[(bx << 5) + by0], off[(bx << 5) + by1 + 1]);

        for (;;) {
            float r20 = (wt0 + q0.w) * 1.0001f + 1e-6f;
            float r21 = (wt1 + q1.w) * 1.0001f + 1e-6f;
            float XL = XMIN + bx0 * BW, XR = XMIN + (bx1 + 1) * BW;
            float YL = XMIN + by0 * BW, YU = XMIN + (by1 + 1) * BW;

            auto need = [&](float g0, float g1) {
                float u = fmaxf(g0 - SAFE, 0.0f), v = fmaxf(g1 - SAFE, 0.0f);
                return (u * u < r20) || (v * v < r21);
            };
            bool nL = (bx0 > 0)       && need(q0.x - XL, q1.x - XL);
            bool nR = (bx1 < NBX - 1) && need(XR - q0.x, XR - q1.x);
            bool nD = (by0 > 0)       && need(q0.y - YL, q1.y - YL);
            bool nU = (by1 < NBY - 1) && need(YU - q0.y, YU - q1.y);
            if (!(nL || nR || nD || nU)) break;

            float kL = nL ? fminf(q0.x - XL, q1.x - XL) : FLT_MAX;
            float kR = nR ? fminf(XR - q0.x, XR - q1.x) : FLT_MAX;
            float kD = nD ? fminf(q0.y - YL, q1.y - YL) : FLT_MAX;
            float kU = nU ? fminf(YU - q0.y, YU - q1.y) : FLT_MAX;

            if (kL <= kR && kL <= kD && kL <= kU) {
                bx0--; process(off[(bx0 << 5) + by0], off[(bx0 << 5) + by1 + 1]);
            } else if (kR <= kD && kR <= kU) {
                bx1++; process(off[(bx1 << 5) + by0], off[(bx1 << 5) + by1 + 1]);
            } else if (kD <= kU) {
                by0--;
                for (int bx = bx0; bx <= bx1; ++bx)
                    process(off[(bx << 5) + by0], off[(bx << 5) + by0 + 1]);
            } else {
                by1++;
                for (int bx = bx0; bx <= bx1; ++bx)
                    process(off[(bx << 5) + by1], off[(bx << 5) + by1 + 1]);
            }
        }

        float l15 = __shfl_sync(FULLM, ld, 15);
        float l31 = __shfl_sync(FULLM, ld, 31);
        if (l15 != FLT_MAX && l31 != FLT_MAX) break;   // list full => exact
    }

    // epilogue: exact weight recomputation from coordinates (faithful to ref)
    const float4 qq = g ? q1 : q0;
    const float4 nbp = rcg[li];
    float dx = qq.x - nbp.x, dy = qq.y - nbp.y, dz = qq.z - nbp.z;
    float dist2 = fmaf(dx, dx, fmaf(dy, dy, dz * dz));
    float w = expf(-0.5f * dist2);

    const int qorig = g_rid[bN + pos0 + g];
    const int qglob = bN + qorig;
    g_idx[qglob * KNN_K + sub] = g_rid[bN + li];
    g_w [qglob * KNN_K + sub] = w;

    float s = w;
    s += __shfl_xor_sync(FULLM, s, 8);
    s += __shfl_xor_sync(FULLM, s, 4);
    s += __shfl_xor_sync(FULLM, s, 2);
    s += __shfl_xor_sync(FULLM, s, 1);
    if (sub == 0) {
        g_Dfwd[qglob] = 0.5f * s;
        g_Drev[qglob] = 0ull;
    }
}

// Reverse-degree scatter with integer fixed-point atomics (deterministic).
__global__ void k_drev(int N, int total_edges)
{
    int e = blockIdx.x * blockDim.x + threadIdx.x;
    if (e >= total_edges) return;
    int q = e >> 4;                 // KNN_K == 16
    int b = q / N;
    float w = g_w[e];
    unsigned long long inc = (unsigned long long)((double)w * 4294967296.0);
    atomicAdd(&g_Drev[b * N + g_idx[e]], inc);
}

// Sparse Laplacian scatter.
__global__ void k_lap(float* __restrict__ out, int N, int total_edges)
{
    int e = blockIdx.x * blockDim.x + threadIdx.x;
    if (e >= total_edges) return;
    int q = e >> 4;
    int b = q / N;
    int i = q - b * N;
    int j = g_idx[e];
    float w = g_w[e];

    float Di = g_Dfwd[q]         + (float)((double)g_Drev[q]         * (0.5 / 4294967296.0));
    float Dj = g_Dfwd[b * N + j] + (float)((double)g_Drev[b * N + j] * (0.5 / 4294967296.0));
    float di = 1.0f / sqrtf(fmaxf(Di, 1e-6f));
    float dj = 1.0f / sqrtf(fmaxf(Dj, 1e-6f));
    float v = -((0.5f * w) * di) * dj;

    float* Lb = out + (size_t)b * N * (size_t)N;
    atomicAdd(Lb + (size_t)i * N + j, v);
    atomicAdd(Lb + (size_t)j * N + i, v);
}

extern "C" void kernel_launch(void* const* d_in, const int* in_sizes, int n_in,
                              void* d_out, int out_size)
{
    const float* xyz = (const float*)d_in[0];
    float* out = (float*)d_out;

    long long inel = in_sizes[0];                       // B*3*N
    int N = (int)((3LL * (long long)out_size) / inel);  // (3*B*N^2)/(3*B*N)
    int B = (int)(inel / (3LL * (long long)N));

    int pts = B * N;
    int pb = (pts + 255) / 256;
    k_hist<<<pb, 256>>>(xyz, N, B);
    k_scan<<<B, NB2>>>(B);
    k_reorder<<<pb, 256>>>(xyz, N, B);

    int nb_knn = B * (N / 32);        // KNN blocks (32 queries each)
    int nb_set = B * N;               // one block per output row
    k_knn_init<<<nb_knn + nb_set, TPB>>>(out, N, B, nb_knn);

    int edges = B * N * KNN_K;
    int eb = (edges + 255) / 256;
    k_drev<<<eb, 256>>>(N, edges);
    k_lap<<<eb, 256>>>(out, N, edges);
}

// round 6
// speedup vs baseline: 1.0128x; 1.0128x over previous
#include <cuda_runtime.h>
#include <math.h>
#include <float.h>

#define TPB    512
#define KNN_K  16
#define NBUCK  64
#define FULLM  0xFFFFFFFFu
#define XMIN   (-4.8f)
#define XMAX   ( 4.8f)
#define BW     ((XMAX - XMIN) / (float)NBUCK)
#define INVBW  ((float)NBUCK / (XMAX - XMIN))
#define SAFE   1e-5f

// scratch (static device arrays; allocation-free rule)
__device__ int                g_idx [65536 * KNN_K];
__device__ float              g_w   [65536 * KNN_K];
__device__ float              g_Dfwd[65536];
__device__ unsigned long long g_Drev[65536];

// bucket-build scratch
__device__ int            g_hist[16 * NBUCK];        // zero-init; re-zeroed by k_scan
__device__ int            g_off [16 * (NBUCK + 1)];
__device__ int            g_cur [16 * NBUCK];
__device__ float4         g_rc  [65536];             // reordered (x,y,z,|p|^2)
__device__ unsigned short g_rid [65536];             // orig index per position

__device__ __forceinline__ int bucket_of_x(float x) {
    int ib = (int)((x - XMIN) * INVBW);
    return min(max(ib, 0), NBUCK - 1);
}

// ---------- prepass ----------
__global__ void k_hist(const float* __restrict__ xyz, int N, int B)
{
    int t = blockIdx.x * blockDim.x + threadIdx.x;
    if (t >= B * N) return;
    g_Drev[t] = 0ull;                       // pre-zero for epilogue atomics
    int b = t / N, n = t - b * N;
    float x = xyz[(size_t)b * 3 * N + n];
    atomicAdd(&g_hist[b * NBUCK + bucket_of_x(x)], 1);
}

__global__ void k_scan(int B)
{
    int warp = threadIdx.x >> 5, lane = threadIdx.x & 31;
    if (warp >= B) return;
    int base = warp * NBUCK;
    int v0 = g_hist[base + lane];
    int v1 = g_hist[base + 32 + lane];
    int s0 = v0, s1 = v1;
    for (int d = 1; d < 32; d <<= 1) {
        int t0 = __shfl_up_sync(FULLM, s0, d);
        int t1 = __shfl_up_sync(FULLM, s1, d);
        if (lane >= d) { s0 += t0; s1 += t1; }
    }
    s1 += __shfl_sync(FULLM, s0, 31);
    int ob = warp * (NBUCK + 1);
    if (lane == 0) g_off[ob] = 0;
    g_off[ob + 1 + lane]  = s0;
    g_off[ob + 33 + lane] = s1;
    g_cur[base + lane]      = s0 - v0;
    g_cur[base + 32 + lane] = s1 - v1;
    g_hist[base + lane] = 0;                 // ready for next graph replay
    g_hist[base + 32 + lane] = 0;
}

__global__ void k_reorder(const float* __restrict__ xyz, int N, int B)
{
    int t = blockIdx.x * blockDim.x + threadIdx.x;
    if (t >= B * N) return;
    int b = t / N, n = t - b * N;
    const float* X = xyz + (size_t)b * 3 * N;
    float x = X[n], y = X[N + n], z = X[2 * N + n];
    float sq = fmaf(x, x, fmaf(y, y, z * z));
    int pos = atomicAdd(&g_cur[b * NBUCK + bucket_of_x(x)], 1);
    g_rc [b * N + pos] = make_float4(x, y, z, sq);
    g_rid[b * N + pos] = (unsigned short)n;
}

// ---------- fused KNN + dense init ----------
// grid = 4*nb_knn blocks. Role: KNN iff (bid & 3)==0 (interleaved so every
// wave mixes 25% KNN with 75% grid-stride memset -> DRAM + ALU both busy).
__global__ void __launch_bounds__(TPB, 3)
k_knn_init(float* __restrict__ out, int N, int B, int nb_knn)
{
    extern __shared__ char smraw[];
    const int tid = threadIdx.x;
    const int bid = blockIdx.x;

    if (bid & 3) {
        // ---------------- memset + diagonal path (grid-stride rows) -------
        int msid  = bid - (bid >> 2) - 1;       // 0 .. 3*nb_knn-1
        int nb_ms = 3 * nb_knn;
        int nrows = B * N;
        int n4 = N >> 2;
        for (int r = msid; r < nrows; r += nb_ms) {
            int b = r / N;
            int i = r - b * N;
            float4* row = reinterpret_cast<float4*>(out + ((size_t)b * N + i) * (size_t)N);
            for (int f = tid; f < n4; f += TPB) {
                int j0 = f << 2;
                float4 v;
                v.x = (j0     == i) ? 1.0f : 0.0f;
                v.y = (j0 + 1 == i) ? 1.0f : 0.0f;
                v.z = (j0 + 2 == i) ? 1.0f : 0.0f;
                v.w = (j0 + 3 == i) ? 1.0f : 0.0f;
                row[f] = v;
            }
        }
        return;
    }

    // ---------------- KNN path (round-4 smem-cached, 1-D buckets) ---------
    float4*         rc  = reinterpret_cast<float4*>(smraw);            // N float4
    unsigned short* rid = reinterpret_cast<unsigned short*>(rc + N);   // N ushort
    int*            off = reinterpret_cast<int*>(rid + N);             // NBUCK+1

    const int kb = bid >> 2;                    // knn block id, 0..nb_knn-1
    const int qpb = (TPB / 32) * 2;             // 32 queries per block
    const int blocks_per_b = N / qpb;
    const int b = kb / blocks_per_b;
    const int qbase = (kb - b * blocks_per_b) * qpb;
    const int bN = b * N;

    for (int n = tid; n < N; n += TPB) rc[n]  = g_rc[bN + n];
    for (int n = tid; n < N; n += TPB) rid[n] = g_rid[bN + n];
    if (tid <= NBUCK) off[tid] = g_off[b * (NBUCK + 1) + tid];
    __syncthreads();

    const int warp = tid >> 5, lane = tid & 31;
    const int g = lane >> 4, sub = lane & 15;
    const int pos0 = qbase + warp * 2;          // bucket-sorted positions
    const float4 q0 = rc[pos0];
    const float4 q1 = rc[pos0 + 1];

    const float a0x = -2.0f * q0.x, a0y = -2.0f * q0.y, a0z = -2.0f * q0.z;
    const float a1x = -2.0f * q1.x, a1y = -2.0f * q1.y, a1z = -2.0f * q1.z;

    // sorted-across-lanes top-16 in e-space; li = POSITION in rc
    float ld = FLT_MAX; int li = 0;
    float wt0 = FLT_MAX, wt1 = FLT_MAX;

    auto process = [&](int start, int end) {
        for (int p = start; p < end; p += 32) {
            int pp = p + lane;
            bool valid = pp < end;
            float4 c = rc[valid ? pp : end - 1];
            float e0 = fmaf(a0x, c.x, fmaf(a0y, c.y, fmaf(a0z, c.z, c.w)));
            float e1 = fmaf(a1x, c.x, fmaf(a1y, c.y, fmaf(a1z, c.z, c.w)));
            unsigned bal0 = __ballot_sync(FULLM, valid && (e0 < wt0));
            unsigned bal1 = __ballot_sync(FULLM, valid && (e1 < wt1));
            if ((bal0 | bal1) == 0u) continue;
            do {
                int s0 = __ffs(bal0) - 1;
                int s1 = __ffs(bal1) - 1;
                float dd0 = __shfl_sync(FULLM, e0, s0 & 31);
                float dd1 = __shfl_sync(FULLM, e1, s1 & 31);
                bool have = g ? (bal1 != 0u) : (bal0 != 0u);
                float dd = g ? dd1 : dd0;
                int   jj = p + ((g ? s1 : s0) & 31);
                bool pr = have && (dd < ld);
                unsigned pb = __ballot_sync(FULLM, pr);
                float sld = __shfl_up_sync(FULLM, ld, 1);
                int   sli = __shfl_up_sync(FULLM, li, 1);
                bool prevpr = (sub > 0) && ((pb >> (lane - 1)) & 1u);
                if (pr) { ld = prevpr ? sld : dd; li = prevpr ? sli : jj; }
                bal0 &= bal0 - 1;
                bal1 &= bal1 - 1;
            } while (bal0 | bal1);
            wt0 = __shfl_sync(FULLM, ld, 15);
            wt1 = __shfl_sync(FULLM, ld, 31);
        }
    };

    // buckets of the two queries (binary search over off[], warp-uniform)
    int blo, bhi;
    {
        int lo = 0, hi = NBUCK - 1;
        while (lo < hi) { int mid = (lo + hi + 1) >> 1; if (off[mid] <= pos0) lo = mid; else hi = mid - 1; }
        blo = lo;
        lo = blo; hi = NBUCK - 1;
        int p1 = pos0 + 1;
        while (lo < hi) { int mid = (lo + hi + 1) >> 1; if (off[mid] <= p1) lo = mid; else hi = mid - 1; }
        bhi = lo;
    }

    process(off[blo], off[bhi + 1]);

    bool leftOpen = blo > 0, rightOpen = bhi < NBUCK - 1;
    while (leftOpen || rightOpen) {
        float r20 = (wt0 + q0.w) * 1.0001f + 1e-6f;   // d^2 bound, slack for fp
        float r21 = (wt1 + q1.w) * 1.0001f + 1e-6f;
        float LBx = XMIN + blo * BW;
        float RBx = XMIN + (bhi + 1) * BW;
        if (leftOpen) {
            float gl0 = fmaxf(q0.x - LBx - SAFE, 0.0f);
            float gl1 = fmaxf(q1.x - LBx - SAFE, 0.0f);
            if (gl0 * gl0 >= r20 && gl1 * gl1 >= r21) leftOpen = false;
        }
        if (rightOpen) {
            float gr0 = fmaxf(RBx - q0.x - SAFE, 0.0f);
            float gr1 = fmaxf(RBx - q1.x - SAFE, 0.0f);
            if (gr0 * gr0 >= r20 && gr1 * gr1 >= r21) rightOpen = false;
        }
        if (!(leftOpen || rightOpen)) break;
        bool goLeft = (leftOpen && rightOpen) ? ((q0.x - LBx) < (RBx - q1.x)) : leftOpen;
        if (goLeft) {
            blo--;
            process(off[blo], off[blo + 1]);
            leftOpen = blo > 0;
        } else {
            bhi++;
            process(off[bhi], off[bhi + 1]);
            rightOpen = bhi < NBUCK - 1;
        }
    }

    // epilogue: exact weight recomputation from coordinates (faithful to ref)
    const float4 qq = g ? q1 : q0;
    const float4 nbp = rc[li];
    float dx = qq.x - nbp.x, dy = qq.y - nbp.y, dz = qq.z - nbp.z;
    float dist2 = fmaf(dx, dx, fmaf(dy, dy, dz * dz));
    float w = expf(-0.5f * dist2);

    const int qorig = rid[pos0 + g];
    const int qglob = bN + qorig;
    const int norig = rid[li];
    g_idx[qglob * KNN_K + sub] = norig;
    g_w [qglob * KNN_K + sub] = w;

    // reverse-degree scatter folded in (fixed-point => deterministic)
    unsigned long long inc = (unsigned long long)((double)w * 4294967296.0);
    atomicAdd(&g_Drev[bN + norig], inc);

    float s = w;
    s += __shfl_xor_sync(FULLM, s, 8);
    s += __shfl_xor_sync(FULLM, s, 4);
    s += __shfl_xor_sync(FULLM, s, 2);
    s += __shfl_xor_sync(FULLM, s, 1);
    if (sub == 0) g_Dfwd[qglob] = 0.5f * s;
}

// Sparse Laplacian scatter.
__global__ void k_lap(float* __restrict__ out, int N, int total_edges)
{
    int e = blockIdx.x * blockDim.x + threadIdx.x;
    if (e >= total_edges) return;
    int q = e >> 4;
    int b = q / N;
    int i = q - b * N;
    int j = g_idx[e];
    float w = g_w[e];

    float Di = g_Dfwd[q]         + (float)((double)g_Drev[q]         * (0.5 / 4294967296.0));
    float Dj = g_Dfwd[b * N + j] + (float)((double)g_Drev[b * N + j] * (0.5 / 4294967296.0));
    float di = 1.0f / sqrtf(fmaxf(Di, 1e-6f));
    float dj = 1.0f / sqrtf(fmaxf(Dj, 1e-6f));
    float v = -((0.5f * w) * di) * dj;

    float* Lb = out + (size_t)b * N * (size_t)N;
    atomicAdd(Lb + (size_t)i * N + j, v);
    atomicAdd(Lb + (size_t)j * N + i, v);
}

extern "C" void kernel_launch(void* const* d_in, const int* in_sizes, int n_in,
                              void* d_out, int out_size)
{
    const float* xyz = (const float*)d_in[0];
    float* out = (float*)d_out;

    long long inel = in_sizes[0];                       // B*3*N
    int N = (int)((3LL * (long long)out_size) / inel);  // (3*B*N^2)/(3*B*N)
    int B = (int)(inel / (3LL * (long long)N));

    int pts = B * N;
    int pb = (pts + 255) / 256;
    k_hist<<<pb, 256>>>(xyz, N, B);
    k_scan<<<1, 32 * B>>>(B);
    k_reorder<<<pb, 256>>>(xyz, N, B);

    int nb_knn = B * (N / 32);        // 512 KNN blocks (32 queries each)
    size_t smem = (size_t)N * sizeof(float4) + (size_t)N * sizeof(unsigned short)
                + (size_t)(NBUCK + 1) * sizeof(int);

    cudaFuncSetAttribute(k_knn_init, cudaFuncAttributeMaxDynamicSharedMemorySize, (int)smem);
    k_knn_init<<<4 * nb_knn, TPB, smem>>>(out, N, B, nb_knn);

    int edges = B * N * KNN_K;
    int eb = (edges + 255) / 256;
    k_lap<<<eb, 256>>>(out, N, edges);
}

// round 7
// speedup vs baseline: 1.1134x; 1.0993x over previous
#include <cuda_runtime.h>
#include <math.h>
#include <float.h>

#define TPB    1024
#define KNN_K  16
#define NBUCK  64
#define FULLM  0xFFFFFFFFu
#define XMIN   (-4.8f)
#define XMAX   ( 4.8f)
#define BW     ((XMAX - XMIN) / (float)NBUCK)
#define INVBW  ((float)NBUCK / (XMAX - XMIN))
#define SAFE   1e-5f

// scratch (static device arrays; allocation-free rule)
__device__ int                g_idx [65536 * KNN_K];
__device__ float              g_w   [65536 * KNN_K];
__device__ float              g_Dfwd[65536];
__device__ unsigned long long g_Drev[65536];

// bucket-build scratch
__device__ int            g_hist[16 * NBUCK];        // zero-init; re-zeroed by k_scan
__device__ int            g_off [16 * (NBUCK + 1)];
__device__ int            g_cur [16 * NBUCK];
__device__ float4         g_rc  [65536];             // reordered (x,y,z,|p|^2)
__device__ unsigned short g_rid [65536];             // orig index per position

__device__ __forceinline__ int bucket_of_x(float x) {
    int ib = (int)((x - XMIN) * INVBW);
    return min(max(ib, 0), NBUCK - 1);
}

// ---------- prepass ----------
__global__ void k_hist(const float* __restrict__ xyz, int N, int B)
{
    int t = blockIdx.x * blockDim.x + threadIdx.x;
    if (t >= B * N) return;
    g_Drev[t] = 0ull;                       // pre-zero for epilogue atomics
    int b = t / N, n = t - b * N;
    float x = xyz[(size_t)b * 3 * N + n];
    atomicAdd(&g_hist[b * NBUCK + bucket_of_x(x)], 1);
}

__global__ void k_scan(int B)
{
    int warp = threadIdx.x >> 5, lane = threadIdx.x & 31;
    if (warp >= B) return;
    int base = warp * NBUCK;
    int v0 = g_hist[base + lane];
    int v1 = g_hist[base + 32 + lane];
    int s0 = v0, s1 = v1;
    for (int d = 1; d < 32; d <<= 1) {
        int t0 = __shfl_up_sync(FULLM, s0, d);
        int t1 = __shfl_up_sync(FULLM, s1, d);
        if (lane >= d) { s0 += t0; s1 += t1; }
    }
    s1 += __shfl_sync(FULLM, s0, 31);
    int ob = warp * (NBUCK + 1);
    if (lane == 0) g_off[ob] = 0;
    g_off[ob + 1 + lane]  = s0;
    g_off[ob + 33 + lane] = s1;
    g_cur[base + lane]      = s0 - v0;
    g_cur[base + 32 + lane] = s1 - v1;
    g_hist[base + lane] = 0;                 // ready for next graph replay
    g_hist[base + 32 + lane] = 0;
}

__global__ void k_reorder(const float* __restrict__ xyz, int N, int B)
{
    int t = blockIdx.x * blockDim.x + threadIdx.x;
    if (t >= B * N) return;
    int b = t / N, n = t - b * N;
    const float* X = xyz + (size_t)b * 3 * N;
    float x = X[n], y = X[N + n], z = X[2 * N + n];
    float sq = fmaf(x, x, fmaf(y, y, z * z));
    int pos = atomicAdd(&g_cur[b * NBUCK + bucket_of_x(x)], 1);
    g_rc [b * N + pos] = make_float4(x, y, z, sq);
    g_rid[b * N + pos] = (unsigned short)n;
}

// ---------- fused KNN + dense init ----------
// Blocks [0, nb_knn): KNN, 64 queries each (2/warp). 256 blocks < 296 slots
// (2 blocks/SM via launch_bounds) => ALL KNN runs in wave 1, no tail.
// Blocks [nb_knn, ...): grid-stride memset+diag rows, fill remaining slots.
__global__ void __launch_bounds__(TPB, 2)
k_knn_init(float* __restrict__ out, int N, int B, int nb_knn, int nb_ms)
{
    extern __shared__ char smraw[];
    const int tid = threadIdx.x;
    const int bid = blockIdx.x;

    if (bid >= nb_knn) {
        // ---------------- memset + diagonal path (grid-stride rows) -------
        int msid  = bid - nb_knn;
        int nrows = B * N;
        int n4 = N >> 2;
        for (int r = msid; r < nrows; r += nb_ms) {
            int b = r / N;
            int i = r - b * N;
            float4* row = reinterpret_cast<float4*>(out + ((size_t)b * N + i) * (size_t)N);
            for (int f = tid; f < n4; f += TPB) {
                int j0 = f << 2;
                float4 v;
                v.x = (j0     == i) ? 1.0f : 0.0f;
                v.y = (j0 + 1 == i) ? 1.0f : 0.0f;
                v.z = (j0 + 2 == i) ? 1.0f : 0.0f;
                v.w = (j0 + 3 == i) ? 1.0f : 0.0f;
                row[f] = v;
            }
        }
        return;
    }

    // ---------------- KNN path (smem-cached, 1-D buckets) ---------
    float4*         rc  = reinterpret_cast<float4*>(smraw);            // N float4
    unsigned short* rid = reinterpret_cast<unsigned short*>(rc + N);   // N ushort
    int*            off = reinterpret_cast<int*>(rid + N);             // NBUCK+1

    const int qpb = (TPB / 32) * 2;             // 64 queries per block
    const int blocks_per_b = N / qpb;
    const int b = bid / blocks_per_b;
    const int qbase = (bid - b * blocks_per_b) * qpb;
    const int bN = b * N;

    for (int n = tid; n < N; n += TPB) rc[n]  = g_rc[bN + n];
    for (int n = tid; n < N; n += TPB) rid[n] = g_rid[bN + n];
    if (tid <= NBUCK) off[tid] = g_off[b * (NBUCK + 1) + tid];
    __syncthreads();

    const int warp = tid >> 5, lane = tid & 31;
    const int g = lane >> 4, sub = lane & 15;
    const int pos0 = qbase + warp * 2;          // bucket-sorted positions

    // queries kept ONLY in pre-scaled form to save registers: a = -2q, qw=|q|^2
    float a0x, a0y, a0z, q0w, a1x, a1y, a1z, q1w;
    {
        float4 q0 = rc[pos0];
        float4 q1 = rc[pos0 + 1];
        a0x = -2.0f * q0.x; a0y = -2.0f * q0.y; a0z = -2.0f * q0.z; q0w = q0.w;
        a1x = -2.0f * q1.x; a1y = -2.0f * q1.y; a1z = -2.0f * q1.z; q1w = q1.w;
    }

    // sorted-across-lanes top-16 in e-space; li = POSITION in rc
    float ld = FLT_MAX; int li = 0;
    float wt0 = FLT_MAX, wt1 = FLT_MAX;

    auto process = [&](int start, int end) {
        for (int p = start; p < end; p += 32) {
            int pp = p + lane;
            bool valid = pp < end;
            float4 c = rc[valid ? pp : end - 1];
            float e0 = fmaf(a0x, c.x, fmaf(a0y, c.y, fmaf(a0z, c.z, c.w)));
            float e1 = fmaf(a1x, c.x, fmaf(a1y, c.y, fmaf(a1z, c.z, c.w)));
            unsigned bal0 = __ballot_sync(FULLM, valid && (e0 < wt0));
            unsigned bal1 = __ballot_sync(FULLM, valid && (e1 < wt1));
            if ((bal0 | bal1) == 0u) continue;
            do {
                int s0 = __ffs(bal0) - 1;
                int s1 = __ffs(bal1) - 1;
                float dd0 = __shfl_sync(FULLM, e0, s0 & 31);
                float dd1 = __shfl_sync(FULLM, e1, s1 & 31);
                bool have = g ? (bal1 != 0u) : (bal0 != 0u);
                float dd = g ? dd1 : dd0;
                int   jj = p + ((g ? s1 : s0) & 31);
                bool pr = have && (dd < ld);
                unsigned pb = __ballot_sync(FULLM, pr);
                float sld = __shfl_up_sync(FULLM, ld, 1);
                int   sli = __shfl_up_sync(FULLM, li, 1);
                bool prevpr = (sub > 0) && ((pb >> (lane - 1)) & 1u);
                if (pr) { ld = prevpr ? sld : dd; li = prevpr ? sli : jj; }
                bal0 &= bal0 - 1;
                bal1 &= bal1 - 1;
            } while (bal0 | bal1);
            wt0 = __shfl_sync(FULLM, ld, 15);
            wt1 = __shfl_sync(FULLM, ld, 31);
        }
    };

    // buckets of the two queries (binary search over off[], warp-uniform)
    int blo, bhi;
    {
        int lo = 0, hi = NBUCK - 1;
        while (lo < hi) { int mid = (lo + hi + 1) >> 1; if (off[mid] <= pos0) lo = mid; else hi = mid - 1; }
        blo = lo;
        lo = blo; hi = NBUCK - 1;
        int p1 = pos0 + 1;
        while (lo < hi) { int mid = (lo + hi + 1) >> 1; if (off[mid] <= p1) lo = mid; else hi = mid - 1; }
        bhi = lo;
    }

    process(off[blo], off[bhi + 1]);

    bool leftOpen = blo > 0, rightOpen = bhi < NBUCK - 1;
    while (leftOpen || rightOpen) {
        float qx0 = -0.5f * a0x, qx1 = -0.5f * a1x;
        float r20 = (wt0 + q0w) * 1.0001f + 1e-6f;    // d^2 bound, slack for fp
        float r21 = (wt1 + q1w) * 1.0001f + 1e-6f;
        float LBx = XMIN + blo * BW;
        float RBx = XMIN + (bhi + 1) * BW;
        if (leftOpen) {
            float gl0 = fmaxf(qx0 - LBx - SAFE, 0.0f);
            float gl1 = fmaxf(qx1 - LBx - SAFE, 0.0f);
            if (gl0 * gl0 >= r20 && gl1 * gl1 >= r21) leftOpen = false;
        }
        if (rightOpen) {
            float gr0 = fmaxf(RBx - qx0 - SAFE, 0.0f);
            float gr1 = fmaxf(RBx - qx1 - SAFE, 0.0f);
            if (gr0 * gr0 >= r20 && gr1 * gr1 >= r21) rightOpen = false;
        }
        if (!(leftOpen || rightOpen)) break;
        bool goLeft = (leftOpen && rightOpen) ? ((qx0 - LBx) < (RBx - qx1)) : leftOpen;
        if (goLeft) {
            blo--;
            process(off[blo], off[blo + 1]);
            leftOpen = blo > 0;
        } else {
            bhi++;
            process(off[bhi], off[bhi + 1]);
            rightOpen = bhi < NBUCK - 1;
        }
    }

    // epilogue: exact weight recomputation from coordinates (faithful to ref)
    float qx = -0.5f * (g ? a1x : a0x);
    float qy = -0.5f * (g ? a1y : a0y);
    float qz = -0.5f * (g ? a1z : a0z);
    const float4 nbp = rc[li];
    float dx = qx - nbp.x, dy = qy - nbp.y, dz = qz - nbp.z;
    float dist2 = fmaf(dx, dx, fmaf(dy, dy, dz * dz));
    float w = expf(-0.5f * dist2);

    const int qorig = rid[pos0 + g];
    const int qglob = bN + qorig;
    const int norig = rid[li];
    g_idx[qglob * KNN_K + sub] = norig;
    g_w [qglob * KNN_K + sub] = w;

    // reverse-degree scatter folded in (fixed-point => deterministic)
    unsigned long long inc = (unsigned long long)((double)w * 4294967296.0);
    atomicAdd(&g_Drev[bN + norig], inc);

    float s = w;
    s += __shfl_xor_sync(FULLM, s, 8);
    s += __shfl_xor_sync(FULLM, s, 4);
    s += __shfl_xor_sync(FULLM, s, 2);
    s += __shfl_xor_sync(FULLM, s, 1);
    if (sub == 0) g_Dfwd[qglob] = 0.5f * s;
}

// Sparse Laplacian scatter.
__global__ void k_lap(float* __restrict__ out, int N, int total_edges)
{
    int e = blockIdx.x * blockDim.x + threadIdx.x;
    if (e >= total_edges) return;
    int q = e >> 4;
    int b = q / N;
    int i = q - b * N;
    int j = g_idx[e];
    float w = g_w[e];

    float Di = g_Dfwd[q]         + (float)((double)g_Drev[q]         * (0.5 / 4294967296.0));
    float Dj = g_Dfwd[b * N + j] + (float)((double)g_Drev[b * N + j] * (0.5 / 4294967296.0));
    float di = 1.0f / sqrtf(fmaxf(Di, 1e-6f));
    float dj = 1.0f / sqrtf(fmaxf(Dj, 1e-6f));
    float v = -((0.5f * w) * di) * dj;

    float* Lb = out + (size_t)b * N * (size_t)N;
    atomicAdd(Lb + (size_t)i * N + j, v);
    atomicAdd(Lb + (size_t)j * N + i, v);
}

extern "C" void kernel_launch(void* const* d_in, const int* in_sizes, int n_in,
                              void* d_out, int out_size)
{
    const float* xyz = (const float*)d_in[0];
    float* out = (float*)d_out;

    long long inel = in_sizes[0];                       // B*3*N
    int N = (int)((3LL * (long long)out_size) / inel);  // (3*B*N^2)/(3*B*N)
    int B = (int)(inel / (3LL * (long long)N));

    int pts = B * N;
    int pb = (pts + 255) / 256;
    k_hist<<<pb, 256>>>(xyz, N, B);
    k_scan<<<1, 32 * B>>>(B);
    k_reorder<<<pb, 256>>>(xyz, N, B);

    int nb_knn = B * (N / 64);        // 256 KNN blocks (64 queries each)
    int nb_ms  = 1792;                // grid-stride memset blocks
    size_t smem = (size_t)N * sizeof(float4) + (size_t)N * sizeof(unsigned short)
                + (size_t)(NBUCK + 1) * sizeof(int);

    cudaFuncSetAttribute(k_knn_init, cudaFuncAttributeMaxDynamicSharedMemorySize, (int)smem);
    k_knn_init<<<nb_knn + nb_ms, TPB, smem>>>(out, N, B, nb_knn, nb_ms);

    int edges = B * N * KNN_K;
    int eb = (edges + 255) / 256;
    k_lap<<<eb, 256>>>(out, N, edges);
}

// round 8
// speedup vs baseline: 1.1816x; 1.0612x over previous
#include <cuda_runtime.h>
#include <math.h>
#include <float.h>

#define TPB    1024
#define KNN_K  16
#define NBUCK  64
#define FULLM  0xFFFFFFFFu
#define XMIN   (-4.8f)
#define XMAX   ( 4.8f)
#define BW     ((XMAX - XMIN) / (float)NBUCK)
#define INVBW  ((float)NBUCK / (XMAX - XMIN))
#define SAFE   1e-5f

// scratch (static device arrays; allocation-free rule)
__device__ int                g_idx [65536 * KNN_K];
__device__ float              g_w   [65536 * KNN_K];
__device__ float              g_Dfwd[65536];
__device__ unsigned long long g_Drev[65536];

// bucket-build scratch
__device__ int            g_hist[16 * NBUCK];        // zero-init; re-zeroed by k_scan
__device__ int            g_off [16 * (NBUCK + 1)];
__device__ int            g_cur [16 * NBUCK];
__device__ float4         g_rc  [65536];             // reordered (x,y,z,|p|^2)
__device__ unsigned short g_rid [65536];             // orig index per position

__device__ __forceinline__ int bucket_of_x(float x) {
    int ib = (int)((x - XMIN) * INVBW);
    return min(max(ib, 0), NBUCK - 1);
}

// ---------- prepass ----------
__global__ void k_hist(const float* __restrict__ xyz, int N, int B)
{
    int t = blockIdx.x * blockDim.x + threadIdx.x;
    if (t >= B * N) return;
    g_Drev[t] = 0ull;                       // pre-zero for epilogue atomics
    int b = t / N, n = t - b * N;
    float x = xyz[(size_t)b * 3 * N + n];
    atomicAdd(&g_hist[b * NBUCK + bucket_of_x(x)], 1);
}

__global__ void k_scan(int B)
{
    int warp = threadIdx.x >> 5, lane = threadIdx.x & 31;
    if (warp >= B) return;
    int base = warp * NBUCK;
    int v0 = g_hist[base + lane];
    int v1 = g_hist[base + 32 + lane];
    int s0 = v0, s1 = v1;
    for (int d = 1; d < 32; d <<= 1) {
        int t0 = __shfl_up_sync(FULLM, s0, d);
        int t1 = __shfl_up_sync(FULLM, s1, d);
        if (lane >= d) { s0 += t0; s1 += t1; }
    }
    s1 += __shfl_sync(FULLM, s0, 31);
    int ob = warp * (NBUCK + 1);
    if (lane == 0) g_off[ob] = 0;
    g_off[ob + 1 + lane]  = s0;
    g_off[ob + 33 + lane] = s1;
    g_cur[base + lane]      = s0 - v0;
    g_cur[base + 32 + lane] = s1 - v1;
    g_hist[base + lane] = 0;                 // ready for next graph replay
    g_hist[base + 32 + lane] = 0;
}

__global__ void k_reorder(const float* __restrict__ xyz, int N, int B)
{
    int t = blockIdx.x * blockDim.x + threadIdx.x;
    if (t >= B * N) return;
    int b = t / N, n = t - b * N;
    const float* X = xyz + (size_t)b * 3 * N;
    float x = X[n], y = X[N + n], z = X[2 * N + n];
    float sq = fmaf(x, x, fmaf(y, y, z * z));
    int pos = atomicAdd(&g_cur[b * NBUCK + bucket_of_x(x)], 1);
    g_rc [b * N + pos] = make_float4(x, y, z, sq);
    g_rid[b * N + pos] = (unsigned short)n;
}

// ---------- fused KNN + dense init ----------
// Blocks [0, nb_knn): KNN, 64 queries each (2/warp), all in wave 1.
// Blocks [nb_knn, ...): grid-stride zero-fill rows (lean: constant float4
// streaming stores, diagonal patched afterwards by the owning thread).
__global__ void __launch_bounds__(TPB, 2)
k_knn_init(float* __restrict__ out, int N, int B, int nb_knn, int nb_ms)
{
    extern __shared__ char smraw[];
    const int tid = threadIdx.x;
    const int bid = blockIdx.x;

    if (bid >= nb_knn) {
        // ------------- zero-fill + diagonal (lean inner loop) -------------
        const float4 z4 = make_float4(0.0f, 0.0f, 0.0f, 0.0f);
        int msid  = bid - nb_knn;
        int nrows = B * N;
        int n4 = N >> 2;
        for (int r = msid; r < nrows; r += nb_ms) {
            int b = r / N;
            int i = r - b * N;
            float4* row = reinterpret_cast<float4*>(out + ((size_t)b * N + i) * (size_t)N);
            #pragma unroll 2
            for (int f = tid; f < n4; f += TPB)
                __stcs(row + f, z4);
            // diagonal patch: same thread that zeroed float4 (i>>2) rewrites it
            int fd = i >> 2;
            if (tid == (fd & (TPB - 1))) {
                float4 v = z4;
                ((float*)&v)[i & 3] = 1.0f;
                __stcs(row + fd, v);
            }
        }
        return;
    }

    // ---------------- KNN path (smem-cached, 1-D buckets) ---------
    float4*         rc  = reinterpret_cast<float4*>(smraw);            // N float4
    unsigned short* rid = reinterpret_cast<unsigned short*>(rc + N);   // N ushort
    int*            off = reinterpret_cast<int*>(rid + N);             // NBUCK+1

    const int qpb = (TPB / 32) * 2;             // 64 queries per block
    const int blocks_per_b = N / qpb;
    const int b = bid / blocks_per_b;
    const int qbase = (bid - b * blocks_per_b) * qpb;
    const int bN = b * N;

    for (int n = tid; n < N; n += TPB) rc[n]  = g_rc[bN + n];
    for (int n = tid; n < N; n += TPB) rid[n] = g_rid[bN + n];
    if (tid <= NBUCK) off[tid] = g_off[b * (NBUCK + 1) + tid];
    __syncthreads();

    const int warp = tid >> 5, lane = tid & 31;
    const int g = lane >> 4, sub = lane & 15;
    const int pos0 = qbase + warp * 2;          // bucket-sorted positions

    // queries kept ONLY in pre-scaled form to save registers: a = -2q, qw=|q|^2
    float a0x, a0y, a0z, q0w, a1x, a1y, a1z, q1w;
    {
        float4 q0 = rc[pos0];
        float4 q1 = rc[pos0 + 1];
        a0x = -2.0f * q0.x; a0y = -2.0f * q0.y; a0z = -2.0f * q0.z; q0w = q0.w;
        a1x = -2.0f * q1.x; a1y = -2.0f * q1.y; a1z = -2.0f * q1.z; q1w = q1.w;
    }

    // sorted-across-lanes top-16 in e-space; li = POSITION in rc
    float ld = FLT_MAX; int li = 0;
    float wt0 = FLT_MAX, wt1 = FLT_MAX;

    auto process = [&](int start, int end) {
        for (int p = start; p < end; p += 32) {
            int pp = p + lane;
            bool valid = pp < end;
            float4 c = rc[valid ? pp : end - 1];
            float e0 = fmaf(a0x, c.x, fmaf(a0y, c.y, fmaf(a0z, c.z, c.w)));
            float e1 = fmaf(a1x, c.x, fmaf(a1y, c.y, fmaf(a1z, c.z, c.w)));
            unsigned bal0 = __ballot_sync(FULLM, valid && (e0 < wt0));
            unsigned bal1 = __ballot_sync(FULLM, valid && (e1 < wt1));
            if ((bal0 | bal1) == 0u) continue;
            do {
                int s0 = __ffs(bal0) - 1;
                int s1 = __ffs(bal1) - 1;
                float dd0 = __shfl_sync(FULLM, e0, s0 & 31);
                float dd1 = __shfl_sync(FULLM, e1, s1 & 31);
                bool have = g ? (bal1 != 0u) : (bal0 != 0u);
                float dd = g ? dd1 : dd0;
                int   jj = p + ((g ? s1 : s0) & 31);
                bool pr = have && (dd < ld);
                unsigned pb = __ballot_sync(FULLM, pr);
                float sld = __shfl_up_sync(FULLM, ld, 1);
                int   sli = __shfl_up_sync(FULLM, li, 1);
                bool prevpr = (sub > 0) && ((pb >> (lane - 1)) & 1u);
                if (pr) { ld = prevpr ? sld : dd; li = prevpr ? sli : jj; }
                bal0 &= bal0 - 1;
                bal1 &= bal1 - 1;
            } while (bal0 | bal1);
            wt0 = __shfl_sync(FULLM, ld, 15);
            wt1 = __shfl_sync(FULLM, ld, 31);
        }
    };

    // buckets of the two queries (binary search over off[], warp-uniform)
    int blo, bhi;
    {
        int lo = 0, hi = NBUCK - 1;
        while (lo < hi) { int mid = (lo + hi + 1) >> 1; if (off[mid] <= pos0) lo = mid; else hi = mid - 1; }
        blo = lo;
        lo = blo; hi = NBUCK - 1;
        int p1 = pos0 + 1;
        while (lo < hi) { int mid = (lo + hi + 1) >> 1; if (off[mid] <= p1) lo = mid; else hi = mid - 1; }
        bhi = lo;
    }

    process(off[blo], off[bhi + 1]);

    bool leftOpen = blo > 0, rightOpen = bhi < NBUCK - 1;
    while (leftOpen || rightOpen) {
        float qx0 = -0.5f * a0x, qx1 = -0.5f * a1x;
        float r20 = (wt0 + q0w) * 1.0001f + 1e-6f;    // d^2 bound, slack for fp
        float r21 = (wt1 + q1w) * 1.0001f + 1e-6f;
        float LBx = XMIN + blo * BW;
        float RBx = XMIN + (bhi + 1) * BW;
        if (leftOpen) {
            float gl0 = fmaxf(qx0 - LBx - SAFE, 0.0f);
            float gl1 = fmaxf(qx1 - LBx - SAFE, 0.0f);
            if (gl0 * gl0 >= r20 && gl1 * gl1 >= r21) leftOpen = false;
        }
        if (rightOpen) {
            float gr0 = fmaxf(RBx - qx0 - SAFE, 0.0f);
            float gr1 = fmaxf(RBx - qx1 - SAFE, 0.0f);
            if (gr0 * gr0 >= r20 && gr1 * gr1 >= r21) rightOpen = false;
        }
        if (!(leftOpen || rightOpen)) break;
        bool goLeft = (leftOpen && rightOpen) ? ((qx0 - LBx) < (RBx - qx1)) : leftOpen;
        if (goLeft) {
            blo--;
            process(off[blo], off[blo + 1]);
            leftOpen = blo > 0;
        } else {
            bhi++;
            process(off[bhi], off[bhi + 1]);
            rightOpen = bhi < NBUCK - 1;
        }
    }

    // epilogue: exact weight recomputation from coordinates (faithful to ref)
    float qx = -0.5f * (g ? a1x : a0x);
    float qy = -0.5f * (g ? a1y : a0y);
    float qz = -0.5f * (g ? a1z : a0z);
    const float4 nbp = rc[li];
    float dx = qx - nbp.x, dy = qy - nbp.y, dz = qz - nbp.z;
    float dist2 = fmaf(dx, dx, fmaf(dy, dy, dz * dz));
    float w = expf(-0.5f * dist2);

    const int qorig = rid[pos0 + g];
    const int qglob = bN + qorig;
    const int norig = rid[li];
    g_idx[qglob * KNN_K + sub] = norig;
    g_w [qglob * KNN_K + sub] = w;

    // reverse-degree scatter folded in (fixed-point => deterministic)
    unsigned long long inc = (unsigned long long)((double)w * 4294967296.0);
    atomicAdd(&g_Drev[bN + norig], inc);

    float s = w;
    s += __shfl_xor_sync(FULLM, s, 8);
    s += __shfl_xor_sync(FULLM, s, 4);
    s += __shfl_xor_sync(FULLM, s, 2);
    s += __shfl_xor_sync(FULLM, s, 1);
    if (sub == 0) g_Dfwd[qglob] = 0.5f * s;
}

// Sparse Laplacian scatter.
__global__ void k_lap(float* __restrict__ out, int N, int total_edges)
{
    int e = blockIdx.x * blockDim.x + threadIdx.x;
    if (e >= total_edges) return;
    int q = e >> 4;
    int b = q / N;
    int i = q - b * N;
    int j = g_idx[e];
    float w = g_w[e];

    float Di = g_Dfwd[q]         + (float)((double)g_Drev[q]         * (0.5 / 4294967296.0));
    float Dj = g_Dfwd[b * N + j] + (float)((double)g_Drev[b * N + j] * (0.5 / 4294967296.0));
    float di = 1.0f / sqrtf(fmaxf(Di, 1e-6f));
    float dj = 1.0f / sqrtf(fmaxf(Dj, 1e-6f));
    float v = -((0.5f * w) * di) * dj;

    float* Lb = out + (size_t)b * N * (size_t)N;
    atomicAdd(Lb + (size_t)i * N + j, v);
    atomicAdd(Lb + (size_t)j * N + i, v);
}

extern "C" void kernel_launch(void* const* d_in, const int* in_sizes, int n_in,
                              void* d_out, int out_size)
{
    const float* xyz = (const float*)d_in[0];
    float* out = (float*)d_out;

    long long inel = in_sizes[0];                       // B*3*N
    int N = (int)((3LL * (long long)out_size) / inel);  // (3*B*N^2)/(3*B*N)
    int B = (int)(inel / (3LL * (long long)N));

    int pts = B * N;
    int pb = (pts + 255) / 256;
    k_hist<<<pb, 256>>>(xyz, N, B);
    k_scan<<<1, 32 * B>>>(B);
    k_reorder<<<pb, 256>>>(xyz, N, B);

    int nb_knn = B * (N / 64);        // 256 KNN blocks (64 queries each)
    int nb_ms  = 1792;                // grid-stride zero-fill blocks
    size_t smem = (size_t)N * sizeof(float4) + (size_t)N * sizeof(unsigned short)
                + (size_t)(NBUCK + 1) * sizeof(int);

    cudaFuncSetAttribute(k_knn_init, cudaFuncAttributeMaxDynamicSharedMemorySize, (int)smem);
    k_knn_init<<<nb_knn + nb_ms, TPB, smem>>>(out, N, B, nb_knn, nb_ms);

    int edges = B * N * KNN_K;
    int eb = (edges + 255) / 256;
    k_lap<<<eb, 256>>>(out, N, edges);
}